// round 3
// baseline (speedup 1.0000x reference)
#include <cuda_runtime.h>
#include <cstddef>

// ---------------------------------------------------------------------------
// Problem constants
// ---------------------------------------------------------------------------
#define BATCH    2
#define SEQ      2048
#define HID      2048
#define HEADS    16
#define HDIM     128
#define KVRANK   256
#define ATTND    2048
#define ROWS     (BATCH * SEQ)          // 4096
#define KVW      (2 * ATTND)            // 4096
#define EPSV     1e-6f

// ---------------------------------------------------------------------------
// Scratch (static device globals; no allocation allowed)
// ---------------------------------------------------------------------------
__device__ float g_q  [(size_t)ROWS * ATTND];   // 32 MB
__device__ float g_lat[(size_t)ROWS * KVRANK];  //  4 MB
__device__ float g_kv [(size_t)ROWS * KVW];     // 64 MB
__device__ float g_at [(size_t)ROWS * ATTND];   // 32 MB

// ---------------------------------------------------------------------------
// SGEMM: C[M,N] = A[M,K] @ B[K,N], row-major. BM=BN=128, BK=8, 256 threads,
// 8x8 micro-tile split as 4+4 halves (conflict-free float4 smem reads).
// Requires: M%128==0, N%128==0, K%8==0 (true for all calls here).
// ---------------------------------------------------------------------------
__global__ __launch_bounds__(256) void sgemm128(
    const float* __restrict__ A, const float* __restrict__ B,
    float* __restrict__ C, int M, int N, int K)
{
    __shared__ float As[8][128];   // transposed A tile: As[k][m]
    __shared__ float Bs[8][128];   // Bs[k][n]

    const int t  = threadIdx.x;
    const int m0 = blockIdx.y * 128;
    const int n0 = blockIdx.x * 128;
    const int tr = t >> 4;         // 0..15
    const int tc = t & 15;         // 0..15

    const int arow = t >> 1;            // 0..127
    const int akq  = (t & 1) * 4;       // 0 or 4
    const int brow = t >> 5;            // 0..7
    const int bcol = (t & 31) * 4;      // 0..124

    float acc[8][8];
#pragma unroll
    for (int i = 0; i < 8; i++)
#pragma unroll
        for (int j = 0; j < 8; j++) acc[i][j] = 0.f;

    for (int k0 = 0; k0 < K; k0 += 8) {
        float4 av = *(const float4*)&A[(size_t)(m0 + arow) * K + k0 + akq];
        As[akq + 0][arow] = av.x;
        As[akq + 1][arow] = av.y;
        As[akq + 2][arow] = av.z;
        As[akq + 3][arow] = av.w;
        *(float4*)&Bs[brow][bcol] =
            *(const float4*)&B[(size_t)(k0 + brow) * N + n0 + bcol];
        __syncthreads();

#pragma unroll
        for (int kk = 0; kk < 8; kk++) {
            float a[8], b[8];
            *(float4*)&a[0] = *(float4*)&As[kk][tr * 4];
            *(float4*)&a[4] = *(float4*)&As[kk][64 + tr * 4];
            *(float4*)&b[0] = *(float4*)&Bs[kk][tc * 4];
            *(float4*)&b[4] = *(float4*)&Bs[kk][64 + tc * 4];
#pragma unroll
            for (int i = 0; i < 8; i++)
#pragma unroll
                for (int j = 0; j < 8; j++)
                    acc[i][j] += a[i] * b[j];
        }
        __syncthreads();
    }

#pragma unroll
    for (int i = 0; i < 8; i++) {
        int r = m0 + ((i < 4) ? (tr * 4 + i) : (64 + tr * 4 + i - 4));
        float4 c0 = make_float4(acc[i][0], acc[i][1], acc[i][2], acc[i][3]);
        float4 c1 = make_float4(acc[i][4], acc[i][5], acc[i][6], acc[i][7]);
        *(float4*)&C[(size_t)r * N + n0 + tc * 4]      = c0;
        *(float4*)&C[(size_t)r * N + n0 + 64 + tc * 4] = c1;
    }
}

// ---------------------------------------------------------------------------
// RMSNorm in-place over rows of [ROWS, KVRANK]
// ---------------------------------------------------------------------------
__global__ __launch_bounds__(256) void rmsnorm_k(float* __restrict__ lat,
                                                 const float* __restrict__ w)
{
    const int r = blockIdx.x;
    const int t = threadIdx.x;
    __shared__ float red[256];
    float v = lat[(size_t)r * KVRANK + t];
    red[t] = v * v;
    __syncthreads();
#pragma unroll
    for (int s = 128; s > 0; s >>= 1) {
        if (t < s) red[t] += red[t + s];
        __syncthreads();
    }
    float ms = red[0] * (1.0f / KVRANK);
    lat[(size_t)r * KVRANK + t] = w[t] * v * rsqrtf(ms + EPSV);
}

// ---------------------------------------------------------------------------
// Flash attention, fp32, causal. One CTA per (head, 64-query tile).
// Q: [ROWS, 2048] (head h at col h*128). KV: [ROWS, 4096] (K cols 0..2047,
// V cols 2048..4095). O: [ROWS, 2048].
// 256 threads. Smem: Q/K/V tiles 64x128 (stride 132), S tile 64x64 (stride 68).
// ---------------------------------------------------------------------------
#define FBM   64
#define QSTR  132
#define SSTR  68
#define FLASH_SMEM ((3 * 64 * QSTR + 64 * SSTR + 256 + 64 + 64) * 4)

__global__ __launch_bounds__(256) void flash_kernel(
    const float* __restrict__ Q, const float* __restrict__ KV,
    float* __restrict__ O)
{
    extern __shared__ float sm[];
    float* Qs   = sm;                    // 64*132
    float* Ks   = Qs + 64 * QSTR;
    float* Vs   = Ks + 64 * QSTR;
    float* Ss   = Vs + 64 * QSTR;        // 64*68
    float* Ssum = Ss + 64 * SSTR;        // 64*4
    float* Asm  = Ssum + 256;            // alpha[64]
    float* Lsm  = Asm + 64;              // l[64]

    const int t    = threadIdx.x;
    const int b    = blockIdx.y >> 4;
    const int h    = blockIdx.y & 15;
    const int mblk = blockIdx.x;
    const int m0   = mblk * FBM;

    // load Q tile
    const size_t qbase = ((size_t)(b * SEQ + m0)) * ATTND + h * HDIM;
#pragma unroll
    for (int i = 0; i < 8; i++) {
        int lin = t + i * 256;           // float4 index within 64x32
        int row = lin >> 5, c4 = lin & 31;
        *(float4*)&Qs[row * QSTR + c4 * 4] =
            *(const float4*)&Q[qbase + (size_t)row * ATTND + c4 * 4];
    }

    const int sr0  = (t >> 4) * 4;       // 4 consecutive rows
    const int n0   = t & 15;             // strided cols: n0 + 16*j
    const int d0   = (t & 15) * 8;       // PV: 8 d-cols
    const int srow = t >> 2;             // softmax row
    const int nseg = t & 3;              // softmax segment

    const float SC = 0.08838834764831845f;   // 1/sqrt(128)

    float m_run = -1e30f, l_run = 0.f;
    float acc[4][8];
#pragma unroll
    for (int i = 0; i < 4; i++)
#pragma unroll
        for (int j = 0; j < 8; j++) acc[i][j] = 0.f;

    for (int nb = 0; nb <= mblk; nb++) {
        const size_t kbase = ((size_t)(b * SEQ + nb * FBM)) * KVW + h * HDIM;
        const size_t vbase = kbase + ATTND;
#pragma unroll
        for (int i = 0; i < 8; i++) {
            int lin = t + i * 256;
            int row = lin >> 5, c4 = lin & 31;
            *(float4*)&Ks[row * QSTR + c4 * 4] =
                *(const float4*)&KV[kbase + (size_t)row * KVW + c4 * 4];
            *(float4*)&Vs[row * QSTR + c4 * 4] =
                *(const float4*)&KV[vbase + (size_t)row * KVW + c4 * 4];
        }
        __syncthreads();

        // --- S = Q K^T for this tile ---
        float sacc[4][4];
#pragma unroll
        for (int i = 0; i < 4; i++)
#pragma unroll
            for (int j = 0; j < 4; j++) sacc[i][j] = 0.f;

#pragma unroll 8
        for (int d4 = 0; d4 < 32; d4++) {
            float4 qa[4], kb[4];
#pragma unroll
            for (int i = 0; i < 4; i++)
                qa[i] = *(float4*)&Qs[(sr0 + i) * QSTR + d4 * 4];
#pragma unroll
            for (int j = 0; j < 4; j++)
                kb[j] = *(float4*)&Ks[(n0 + 16 * j) * QSTR + d4 * 4];
#pragma unroll
            for (int i = 0; i < 4; i++)
#pragma unroll
                for (int j = 0; j < 4; j++)
                    sacc[i][j] += qa[i].x * kb[j].x + qa[i].y * kb[j].y +
                                  qa[i].z * kb[j].z + qa[i].w * kb[j].w;
        }
#pragma unroll
        for (int i = 0; i < 4; i++)
#pragma unroll
            for (int j = 0; j < 4; j++) {
                int kg = nb * FBM + n0 + 16 * j;
                int qg = m0 + sr0 + i;
                Ss[(sr0 + i) * SSTR + n0 + 16 * j] =
                    (kg <= qg) ? sacc[i][j] * SC : -1e30f;
            }
        __syncthreads();

        // --- online softmax for row `srow` (4 threads/row, redundant stats) ---
        float mb = -1e30f;
#pragma unroll 8
        for (int n = 0; n < 64; n++) mb = fmaxf(mb, Ss[srow * SSTR + n]);
        float m_new = fmaxf(m_run, mb);
        float alpha = __expf(m_run - m_new);
        float psum = 0.f;
#pragma unroll
        for (int j = 0; j < 16; j++) {
            int idx = srow * SSTR + nseg * 16 + j;
            float p = __expf(Ss[idx] - m_new);
            Ss[idx] = p;
            psum += p;
        }
        Ssum[srow * 4 + nseg] = psum;
        if (nseg == 0) Asm[srow] = alpha;
        m_run = m_new;
        __syncthreads();

        l_run = l_run * alpha + Ssum[srow * 4 + 0] + Ssum[srow * 4 + 1] +
                Ssum[srow * 4 + 2] + Ssum[srow * 4 + 3];

        // --- O += P V ---
#pragma unroll
        for (int i = 0; i < 4; i++) {
            float a = Asm[sr0 + i];
#pragma unroll
            for (int j = 0; j < 8; j++) acc[i][j] *= a;
        }
#pragma unroll 4
        for (int n = 0; n < 64; n++) {
            float4 v0 = *(float4*)&Vs[n * QSTR + d0];
            float4 v1 = *(float4*)&Vs[n * QSTR + d0 + 4];
#pragma unroll
            for (int i = 0; i < 4; i++) {
                float p = Ss[(sr0 + i) * SSTR + n];
                acc[i][0] += p * v0.x; acc[i][1] += p * v0.y;
                acc[i][2] += p * v0.z; acc[i][3] += p * v0.w;
                acc[i][4] += p * v1.x; acc[i][5] += p * v1.y;
                acc[i][6] += p * v1.z; acc[i][7] += p * v1.w;
            }
        }
        __syncthreads();
    }

    if (nseg == 0) Lsm[srow] = l_run;
    __syncthreads();

#pragma unroll
    for (int i = 0; i < 4; i++) {
        float inv = 1.f / Lsm[sr0 + i];
        size_t obase = ((size_t)(b * SEQ + m0 + sr0 + i)) * ATTND + h * HDIM + d0;
        float4 o0 = make_float4(acc[i][0] * inv, acc[i][1] * inv,
                                acc[i][2] * inv, acc[i][3] * inv);
        float4 o1 = make_float4(acc[i][4] * inv, acc[i][5] * inv,
                                acc[i][6] * inv, acc[i][7] * inv);
        *(float4*)&O[obase]     = o0;
        *(float4*)&O[obase + 4] = o1;
    }
}

// ---------------------------------------------------------------------------
// Launch
// ---------------------------------------------------------------------------
extern "C" void kernel_launch(void* const* d_in, const int* in_sizes, int n_in,
                              void* d_out, int out_size)
{
    const float* x     = (const float*)d_in[0];
    const float* Wq    = (const float*)d_in[1];
    const float* Wkd   = (const float*)d_in[2];
    const float* wnorm = (const float*)d_in[3];
    const float* Wku   = (const float*)d_in[4];
    const float* Wo    = (const float*)d_in[5];
    float* out = (float*)d_out;

    float *q, *lat, *kv, *at;
    cudaGetSymbolAddress((void**)&q,   g_q);
    cudaGetSymbolAddress((void**)&lat, g_lat);
    cudaGetSymbolAddress((void**)&kv,  g_kv);
    cudaGetSymbolAddress((void**)&at,  g_at);

    cudaFuncSetAttribute(flash_kernel,
                         cudaFuncAttributeMaxDynamicSharedMemorySize,
                         FLASH_SMEM);

    // q = x @ Wq                       [4096,2048] x [2048,2048]
    sgemm128<<<dim3(ATTND / 128, ROWS / 128), 256>>>(x, Wq, q, ROWS, ATTND, HID);
    // latent = x @ Wkv_down            [4096,2048] x [2048,256]
    sgemm128<<<dim3(KVRANK / 128, ROWS / 128), 256>>>(x, Wkd, lat, ROWS, KVRANK, HID);
    // rmsnorm(latent)
    rmsnorm_k<<<ROWS, 256>>>(lat, wnorm);
    // kv = latent @ Wkv_up             [4096,256] x [256,4096]
    sgemm128<<<dim3(KVW / 128, ROWS / 128), 256>>>(lat, Wku, kv, ROWS, KVW, KVRANK);
    // attention
    flash_kernel<<<dim3(SEQ / FBM, BATCH * HEADS), 256, FLASH_SMEM>>>(q, kv, at);
    // out = attn @ Wo                  [4096,2048] x [2048,2048]
    sgemm128<<<dim3(HID / 128, ROWS / 128), 256>>>(at, Wo, out, ROWS, HID, ATTND);
}

// round 5
// speedup vs baseline: 2.9422x; 2.9422x over previous
#include <cuda_runtime.h>
#include <cstdint>
#include <cstddef>

// ---------------------------------------------------------------------------
// Problem constants
// ---------------------------------------------------------------------------
#define BATCH    2
#define SEQ      2048
#define HID      2048
#define HEADS    16
#define HDIM     128
#define KVRANK   256
#define ATTND    2048
#define ROWS     (BATCH * SEQ)          // 4096
#define KVW      (2 * ATTND)            // 4096
#define EPSV     1e-6f

// ---------------------------------------------------------------------------
// Scratch (static device globals; no allocation allowed)
// ---------------------------------------------------------------------------
__device__ float g_q  [(size_t)ROWS * ATTND];   // 32 MB
__device__ float g_lat[(size_t)ROWS * KVRANK];  //  4 MB
__device__ float g_kv [(size_t)ROWS * KVW];     // 64 MB
__device__ float g_at [(size_t)ROWS * ATTND];   // 32 MB

// ---------------------------------------------------------------------------
// TF32 helpers
// ---------------------------------------------------------------------------
__device__ __forceinline__ uint32_t f2tf(float x) {
    uint32_t r;
    asm("cvt.rna.tf32.f32 %0, %1;" : "=r"(r) : "f"(x));
    return r;
}
__device__ __forceinline__ float f2tff(float x) {
    return __uint_as_float(f2tf(x));
}
__device__ __forceinline__ void mma8(float* d, const uint32_t* a,
                                     uint32_t b0, uint32_t b1) {
    asm volatile(
        "mma.sync.aligned.m16n8k8.row.col.f32.tf32.tf32.f32 "
        "{%0,%1,%2,%3}, {%4,%5,%6,%7}, {%8,%9}, {%0,%1,%2,%3};"
        : "+f"(d[0]), "+f"(d[1]), "+f"(d[2]), "+f"(d[3])
        : "r"(a[0]), "r"(a[1]), "r"(a[2]), "r"(a[3]), "r"(b0), "r"(b1));
}

// ---------------------------------------------------------------------------
// TF32 tensor-core GEMM: C[M,N] = A[M,K] @ B[K,N], row-major fp32 in/out.
// BM=128, BN=128, BK=16, 256 threads = 8 warps (4 along M x 2 along N),
// warp tile 32x64, double-buffered smem, RNA tf32 rounding at STS.
// Requires M%128==0, N%128==0, K%16==0.
// ---------------------------------------------------------------------------
#define TSTR 136   // smem row stride (words): bank = k*8 + g  -> conflict-free frags

__global__ __launch_bounds__(256) void gemm_tf32(
    const float* __restrict__ A, const float* __restrict__ B,
    float* __restrict__ C, int M, int N, int K)
{
    __shared__ float As[2][16 * TSTR];   // stored [k][m]
    __shared__ float Bs[2][16 * TSTR];   // stored [k][n]

    const int t     = threadIdx.x;
    const int lane  = t & 31;
    const int wid   = t >> 5;
    const int g     = lane >> 2;     // 0..7
    const int tq    = lane & 3;      // 0..3
    const int warpm = wid & 3;       // 0..3
    const int warpn = wid >> 2;      // 0..1
    const int m0 = blockIdx.y * 128;
    const int n0 = blockIdx.x * 128;

    float4 pa[2], pb[2];

    auto ldA = [&](int k0) {
#pragma unroll
        for (int i = 0; i < 2; i++) {
            int lin = t + i * 256;
            int row = lin >> 2, c4 = lin & 3;
            pa[i] = *(const float4*)&A[(size_t)(m0 + row) * K + k0 + c4 * 4];
        }
    };
    auto ldB = [&](int k0) {
#pragma unroll
        for (int i = 0; i < 2; i++) {
            int lin = t + i * 256;
            int row = lin >> 5, c4 = lin & 31;
            pb[i] = *(const float4*)&B[(size_t)(k0 + row) * N + n0 + c4 * 4];
        }
    };
    auto stAB = [&](int buf) {
#pragma unroll
        for (int i = 0; i < 2; i++) {
            int lin = t + i * 256;
            int row = lin >> 2, c4 = lin & 3;            // A: transpose store
            float* ap = As[buf];
            ap[(c4 * 4 + 0) * TSTR + row] = f2tff(pa[i].x);
            ap[(c4 * 4 + 1) * TSTR + row] = f2tff(pa[i].y);
            ap[(c4 * 4 + 2) * TSTR + row] = f2tff(pa[i].z);
            ap[(c4 * 4 + 3) * TSTR + row] = f2tff(pa[i].w);
            int brow = lin >> 5, bc4 = lin & 31;         // B: direct store
            float4 r = make_float4(f2tff(pb[i].x), f2tff(pb[i].y),
                                   f2tff(pb[i].z), f2tff(pb[i].w));
            *(float4*)&Bs[buf][brow * TSTR + bc4 * 4] = r;
        }
    };

    float acc[2][8][4];
#pragma unroll
    for (int mt = 0; mt < 2; mt++)
#pragma unroll
        for (int nt = 0; nt < 8; nt++)
#pragma unroll
            for (int j = 0; j < 4; j++) acc[mt][nt][j] = 0.f;

    ldA(0); ldB(0); stAB(0);
    __syncthreads();

    int buf = 0;
    for (int k0 = 0; k0 < K; k0 += 16) {
        const bool more = (k0 + 16) < K;
        if (more) { ldA(k0 + 16); ldB(k0 + 16); }

        const uint32_t* ap = (const uint32_t*)As[buf];
        const uint32_t* bp = (const uint32_t*)Bs[buf];
#pragma unroll
        for (int ks = 0; ks < 2; ks++) {
            uint32_t af[2][4];
#pragma unroll
            for (int mt = 0; mt < 2; mt++) {
                int mb = warpm * 32 + mt * 16;
                af[mt][0] = ap[(ks * 8 + tq) * TSTR + mb + g];
                af[mt][1] = ap[(ks * 8 + tq) * TSTR + mb + g + 8];
                af[mt][2] = ap[(ks * 8 + tq + 4) * TSTR + mb + g];
                af[mt][3] = ap[(ks * 8 + tq + 4) * TSTR + mb + g + 8];
            }
#pragma unroll
            for (int nt = 0; nt < 8; nt++) {
                int nb = warpn * 64 + nt * 8;
                uint32_t b0 = bp[(ks * 8 + tq) * TSTR + nb + g];
                uint32_t b1 = bp[(ks * 8 + tq + 4) * TSTR + nb + g];
                mma8(acc[0][nt], af[0], b0, b1);
                mma8(acc[1][nt], af[1], b0, b1);
            }
        }
        if (more) {
            stAB(buf ^ 1);
            __syncthreads();
            buf ^= 1;
        }
    }

#pragma unroll
    for (int mt = 0; mt < 2; mt++)
#pragma unroll
        for (int nt = 0; nt < 8; nt++) {
            int row = m0 + warpm * 32 + mt * 16 + g;
            int col = n0 + warpn * 64 + nt * 8 + 2 * tq;
            *(float2*)&C[(size_t)row * N + col] =
                make_float2(acc[mt][nt][0], acc[mt][nt][1]);
            *(float2*)&C[(size_t)(row + 8) * N + col] =
                make_float2(acc[mt][nt][2], acc[mt][nt][3]);
        }
}

// ---------------------------------------------------------------------------
// RMSNorm in-place over rows of [ROWS, KVRANK]
// ---------------------------------------------------------------------------
__global__ __launch_bounds__(256) void rmsnorm_k(float* __restrict__ lat,
                                                 const float* __restrict__ w)
{
    const int r = blockIdx.x;
    const int t = threadIdx.x;
    __shared__ float red[256];
    float v = lat[(size_t)r * KVRANK + t];
    red[t] = v * v;
    __syncthreads();
#pragma unroll
    for (int s = 128; s > 0; s >>= 1) {
        if (t < s) red[t] += red[t + s];
        __syncthreads();
    }
    float ms = red[0] * (1.0f / KVRANK);
    lat[(size_t)r * KVRANK + t] = w[t] * v * rsqrtf(ms + EPSV);
}

// ---------------------------------------------------------------------------
// Flash attention with tf32 mma.sync. Causal.
// BM=128 queries (8 warps x 16 rows), BN=64 keys per iter, D=128.
// Q in registers (A-fragments), K smem stride 132, V smem stride 136
// (each conflict-free for its fragment pattern). FA2 register softmax,
// P C-layout -> A-layout via shuffles.
// ---------------------------------------------------------------------------
#define KSTR 132
#define VSTR 136
#define FLASH_SMEM ((64 * KSTR + 64 * VSTR) * 4)

__global__ __launch_bounds__(256, 1) void flash_tc(
    const float* __restrict__ Q, const float* __restrict__ KV,
    float* __restrict__ O)
{
    extern __shared__ float sm[];
    float* Ks = sm;                 // [64][KSTR]  (key row, d col)
    float* Vs = sm + 64 * KSTR;     // [64][VSTR]  (key row, d col)

    const int t    = threadIdx.x;
    const int lane = t & 31;
    const int wid  = t >> 5;
    const int g    = lane >> 2;
    const int tq   = lane & 3;
    const int b    = blockIdx.y >> 4;
    const int h    = blockIdx.y & 15;
    const int m0   = blockIdx.x * 128;
    const int wrow = m0 + wid * 16;

    // Q fragments: 16 k-tiles (d), 4 regs each, tf32-rounded
    uint32_t qf[16][4];
    const float* Qb = Q + (size_t)(b * SEQ + wrow) * ATTND + h * HDIM;
#pragma unroll
    for (int kt = 0; kt < 16; kt++) {
        qf[kt][0] = f2tf(Qb[(size_t)g * ATTND + kt * 8 + tq]);
        qf[kt][1] = f2tf(Qb[(size_t)(g + 8) * ATTND + kt * 8 + tq]);
        qf[kt][2] = f2tf(Qb[(size_t)g * ATTND + kt * 8 + tq + 4]);
        qf[kt][3] = f2tf(Qb[(size_t)(g + 8) * ATTND + kt * 8 + tq + 4]);
    }

    float oacc[16][4];
#pragma unroll
    for (int nt = 0; nt < 16; nt++)
#pragma unroll
        for (int j = 0; j < 4; j++) oacc[nt][j] = 0.f;

    float mr0 = -1e30f, mr1 = -1e30f, l0 = 0.f, l1 = 0.f;
    const float SC = 0.08838834764831845f;   // 1/sqrt(128)
    const int nkb = 2 * (blockIdx.x + 1);

    for (int kb = 0; kb < nkb; kb++) {
        // --- load K,V tile (tf32-rounded at store) ---
        const float* KVb = KV + (size_t)(b * SEQ + kb * 64) * KVW + h * HDIM;
#pragma unroll
        for (int i = 0; i < 8; i++) {
            int lin = t + i * 256;
            int row = lin >> 5, c4 = lin & 31;
            float4 k4 = *(const float4*)&KVb[(size_t)row * KVW + c4 * 4];
            float4 v4 = *(const float4*)&KVb[(size_t)row * KVW + ATTND + c4 * 4];
            *(float4*)&Ks[row * KSTR + c4 * 4] =
                make_float4(f2tff(k4.x), f2tff(k4.y), f2tff(k4.z), f2tff(k4.w));
            *(float4*)&Vs[row * VSTR + c4 * 4] =
                make_float4(f2tff(v4.x), f2tff(v4.y), f2tff(v4.z), f2tff(v4.w));
        }
        __syncthreads();

        // --- S = Q K^T  (warp: 16 rows x 64 keys = 8 n-tiles) ---
        float sacc[8][4];
#pragma unroll
        for (int nt = 0; nt < 8; nt++)
#pragma unroll
            for (int j = 0; j < 4; j++) sacc[nt][j] = 0.f;

        const uint32_t* kp = (const uint32_t*)Ks;
#pragma unroll
        for (int nt = 0; nt < 8; nt++) {
#pragma unroll
            for (int kt = 0; kt < 16; kt++) {
                uint32_t b0 = kp[(nt * 8 + g) * KSTR + kt * 8 + tq];
                uint32_t b1 = kp[(nt * 8 + g) * KSTR + kt * 8 + tq + 4];
                mma8(sacc[nt], qf[kt], b0, b1);
            }
        }

        // --- scale + causal mask ---
        const int r0 = wrow + g, r1 = r0 + 8;
#pragma unroll
        for (int nt = 0; nt < 8; nt++) {
            int colb = kb * 64 + nt * 8 + 2 * tq;
            sacc[nt][0] = (colb     <= r0) ? sacc[nt][0] * SC : -1e30f;
            sacc[nt][1] = (colb + 1 <= r0) ? sacc[nt][1] * SC : -1e30f;
            sacc[nt][2] = (colb     <= r1) ? sacc[nt][2] * SC : -1e30f;
            sacc[nt][3] = (colb + 1 <= r1) ? sacc[nt][3] * SC : -1e30f;
        }

        // --- online softmax (rows r0, r1 per thread; quad = lanes sharing g) ---
        float mb0 = -1e30f, mb1 = -1e30f;
#pragma unroll
        for (int nt = 0; nt < 8; nt++) {
            mb0 = fmaxf(mb0, fmaxf(sacc[nt][0], sacc[nt][1]));
            mb1 = fmaxf(mb1, fmaxf(sacc[nt][2], sacc[nt][3]));
        }
        mb0 = fmaxf(mb0, __shfl_xor_sync(0xffffffffu, mb0, 1));
        mb0 = fmaxf(mb0, __shfl_xor_sync(0xffffffffu, mb0, 2));
        mb1 = fmaxf(mb1, __shfl_xor_sync(0xffffffffu, mb1, 1));
        mb1 = fmaxf(mb1, __shfl_xor_sync(0xffffffffu, mb1, 2));

        float mn0 = fmaxf(mr0, mb0), mn1 = fmaxf(mr1, mb1);
        float al0 = __expf(mr0 - mn0), al1 = __expf(mr1 - mn1);
        mr0 = mn0; mr1 = mn1;

        float ps0 = 0.f, ps1 = 0.f;
#pragma unroll
        for (int nt = 0; nt < 8; nt++) {
            sacc[nt][0] = __expf(sacc[nt][0] - mn0);
            sacc[nt][1] = __expf(sacc[nt][1] - mn0);
            sacc[nt][2] = __expf(sacc[nt][2] - mn1);
            sacc[nt][3] = __expf(sacc[nt][3] - mn1);
            ps0 += sacc[nt][0] + sacc[nt][1];
            ps1 += sacc[nt][2] + sacc[nt][3];
        }
        ps0 += __shfl_xor_sync(0xffffffffu, ps0, 1);
        ps0 += __shfl_xor_sync(0xffffffffu, ps0, 2);
        ps1 += __shfl_xor_sync(0xffffffffu, ps1, 1);
        ps1 += __shfl_xor_sync(0xffffffffu, ps1, 2);
        l0 = l0 * al0 + ps0;
        l1 = l1 * al1 + ps1;

#pragma unroll
        for (int nt = 0; nt < 16; nt++) {
            oacc[nt][0] *= al0; oacc[nt][1] *= al0;
            oacc[nt][2] *= al1; oacc[nt][3] *= al1;
        }

        // --- O += P V ---
        const uint32_t* vp = (const uint32_t*)Vs;
#pragma unroll
        for (int kt2 = 0; kt2 < 8; kt2++) {
            // convert P (C-layout) -> A-fragment layout via shuffles
            uint32_t pc0 = f2tf(sacc[kt2][0]), pc1 = f2tf(sacc[kt2][1]);
            uint32_t pc2 = f2tf(sacc[kt2][2]), pc3 = f2tf(sacc[kt2][3]);
            int base = lane & ~3;
            int s0 = base + (tq >> 1), s1 = s0 + 2;
            uint32_t x0 = __shfl_sync(0xffffffffu, pc0, s0);
            uint32_t x1 = __shfl_sync(0xffffffffu, pc1, s0);
            uint32_t x2 = __shfl_sync(0xffffffffu, pc2, s0);
            uint32_t x3 = __shfl_sync(0xffffffffu, pc3, s0);
            uint32_t y0 = __shfl_sync(0xffffffffu, pc0, s1);
            uint32_t y1 = __shfl_sync(0xffffffffu, pc1, s1);
            uint32_t y2 = __shfl_sync(0xffffffffu, pc2, s1);
            uint32_t y3 = __shfl_sync(0xffffffffu, pc3, s1);
            uint32_t af[4];
            af[0] = (tq & 1) ? x1 : x0;   // P[g][t]
            af[1] = (tq & 1) ? x3 : x2;   // P[g+8][t]
            af[2] = (tq & 1) ? y1 : y0;   // P[g][t+4]
            af[3] = (tq & 1) ? y3 : y2;   // P[g+8][t+4]
#pragma unroll
            for (int nt2 = 0; nt2 < 16; nt2++) {
                uint32_t b0 = vp[(kt2 * 8 + tq) * VSTR + nt2 * 8 + g];
                uint32_t b1 = vp[(kt2 * 8 + tq + 4) * VSTR + nt2 * 8 + g];
                mma8(oacc[nt2], af, b0, b1);
            }
        }
        __syncthreads();
    }

    // --- epilogue: O = acc / l ---
    const float inv0 = 1.f / l0, inv1 = 1.f / l1;
#pragma unroll
    for (int nt2 = 0; nt2 < 16; nt2++) {
        size_t o0 = (size_t)(b * SEQ + wrow + g) * ATTND + h * HDIM + nt2 * 8 + 2 * tq;
        *(float2*)&O[o0] = make_float2(oacc[nt2][0] * inv0, oacc[nt2][1] * inv0);
        *(float2*)&O[o0 + (size_t)8 * ATTND] =
            make_float2(oacc[nt2][2] * inv1, oacc[nt2][3] * inv1);
    }
}

// ---------------------------------------------------------------------------
// Launch
// ---------------------------------------------------------------------------
extern "C" void kernel_launch(void* const* d_in, const int* in_sizes, int n_in,
                              void* d_out, int out_size)
{
    const float* x     = (const float*)d_in[0];
    const float* Wq    = (const float*)d_in[1];
    const float* Wkd   = (const float*)d_in[2];
    const float* wnorm = (const float*)d_in[3];
    const float* Wku   = (const float*)d_in[4];
    const float* Wo    = (const float*)d_in[5];
    float* out = (float*)d_out;

    float *q, *lat, *kv, *at;
    cudaGetSymbolAddress((void**)&q,   g_q);
    cudaGetSymbolAddress((void**)&lat, g_lat);
    cudaGetSymbolAddress((void**)&kv,  g_kv);
    cudaGetSymbolAddress((void**)&at,  g_at);

    cudaFuncSetAttribute(flash_tc,
                         cudaFuncAttributeMaxDynamicSharedMemorySize,
                         FLASH_SMEM);

    // q = x @ Wq                       [4096,2048] x [2048,2048]
    gemm_tf32<<<dim3(ATTND / 128, ROWS / 128), 256>>>(x, Wq, q, ROWS, ATTND, HID);
    // latent = x @ Wkv_down            [4096,2048] x [2048,256]
    gemm_tf32<<<dim3(KVRANK / 128, ROWS / 128), 256>>>(x, Wkd, lat, ROWS, KVRANK, HID);
    // rmsnorm(latent)
    rmsnorm_k<<<ROWS, 256>>>(lat, wnorm);
    // kv = latent @ Wkv_up             [4096,256] x [256,4096]
    gemm_tf32<<<dim3(KVW / 128, ROWS / 128), 256>>>(lat, Wku, kv, ROWS, KVW, KVRANK);
    // attention
    flash_tc<<<dim3(SEQ / 128, BATCH * HEADS), 256, FLASH_SMEM>>>(q, kv, at);
    // out = attn @ Wo                  [4096,2048] x [2048,2048]
    gemm_tf32<<<dim3(HID / 128, ROWS / 128), 256>>>(at, Wo, out, ROWS, HID, ATTND);
}